// round 8
// baseline (speedup 1.0000x reference)
#include <cuda_runtime.h>
#include <cuda_fp16.h>
#include <cstdint>

#define Bdim 16
#define Ndim 2048
#define Ddim 1024
#define Pdim 2048

// ---------------- device scratch (static; allocation-free rule) ----------------
__device__ __align__(256) __half g_x[(size_t)Bdim * Ndim * Ddim];    // x fp16 [b][n][d]
__device__ __align__(256) __half g_p[(size_t)Pdim * Ddim];           // (proto-0.5) [p][d]
__device__ __align__(256) __half g_pt[(size_t)Ddim * Pdim];          // (proto-0.5)^T [d][p]
__device__ __align__(256) float  g_ZT[(size_t)Bdim * Ndim * Pdim];   // Z^T [b][n][p]
__device__ __align__(256) __half g_a[(size_t)Bdim * Ndim * Pdim];    // quantized exp [b][n][p]
__device__ __align__(256) float  g_rs[(size_t)Bdim * Ndim];          // 0.5 * row-sum of x
__device__ __align__(256) float  g_inv[(size_t)Bdim * Ndim];         // 1/sum(quantized exp)

// ---------------- baseline-PTX helpers (sm_80-class only) ----------------------
__device__ __forceinline__ uint32_t smem_u32_of(const void* p) {
    uint32_t a;
    asm("{ .reg .u64 t; cvta.to.shared.u64 t, %1; cvt.u32.u64 %0, t; }" : "=r"(a) : "l"(p));
    return a;
}
__device__ __forceinline__ void cpasync16(uint32_t s, const void* g) {
    asm volatile("cp.async.cg.shared.global [%0], [%1], 16;" :: "r"(s), "l"(g));
}
#define CP_COMMIT() asm volatile("cp.async.commit_group;")
#define CP_WAIT(n)  asm volatile("cp.async.wait_group %0;" :: "n"(n))

__device__ __forceinline__ void ldsm4(uint32_t* r, uint32_t addr) {
    asm volatile("ldmatrix.sync.aligned.m8n8.x4.shared.b16 {%0,%1,%2,%3}, [%4];"
                 : "=r"(r[0]), "=r"(r[1]), "=r"(r[2]), "=r"(r[3]) : "r"(addr));
}
__device__ __forceinline__ void mma16816(float* c, const uint32_t* a, const uint32_t* b) {
    asm volatile("mma.sync.aligned.m16n8k16.row.col.f32.f16.f16.f32 "
                 "{%0,%1,%2,%3}, {%4,%5,%6,%7}, {%8,%9}, {%0,%1,%2,%3};"
                 : "+f"(c[0]), "+f"(c[1]), "+f"(c[2]), "+f"(c[3])
                 : "r"(a[0]), "r"(a[1]), "r"(a[2]), "r"(a[3]), "r"(b[0]), "r"(b[1]));
}

// ---------------- tiling constants ----------------
// CTA: 128 threads, 2x2 warps, CTA tile 128x128, warp tile 64x64.
static constexpr int KT = 64;                 // fp16 k per stage (128 data bytes/row)
static constexpr int ROWB = 144;              // padded smem row bytes (128 + 16)
static constexpr int TILE_B = 128 * ROWB;     // 18432 per operand tile
static constexpr int STAGE_B = 2 * TILE_B;    // A, B = 36864
static constexpr int NSTG = 3;                // circular pipeline depth
static constexpr int DYN_SMEM = NSTG * STAGE_B;   // 110592; x2 CTAs = 221184 <= 228KB

// load one stage (2 tiles x 128 rows x 128B), 16 cp.async per thread (128 thr)
__device__ __forceinline__ void load_stage(
    const __half* gA, const __half* gB,
    size_t Ks, int k0, uint32_t sbase, int tid)
{
    const __half* G[2] = {gA, gB};
#pragma unroll
    for (int j = 0; j < 16; j++) {
        const int idx = tid + j * 128;        // 0..2047
        const int tile = idx >> 10;
        const int c = idx & 1023;
        const int row = c >> 3, q = c & 7;
        cpasync16(sbase + tile * TILE_B + row * ROWB + q * 16,
                  G[tile] + (size_t)row * Ks + k0 + q * 8);
    }
}

// compute one k64 stage: 4 k16-steps x (4 m-frags x 8 n-frags)
__device__ __forceinline__ void compute_stage(
    uint32_t sbase, int wm, int wn, uint32_t aoff, uint32_t boff,
    float acc[4][8][4])
{
    const uint32_t sA = sbase;
    const uint32_t sB = sbase + TILE_B;
#pragma unroll
    for (int ks = 0; ks < 4; ks++) {
        const uint32_t kb = ks * 32;   // 16 fp16 = 32 bytes
        uint32_t bf[16];
#pragma unroll
        for (int f = 0; f < 4; f++) {
            uint32_t off = (wn * 64 + f * 16) * ROWB + kb + boff;
            ldsm4(bf + f * 4, sB + off);
        }
#pragma unroll
        for (int mf = 0; mf < 4; mf++) {
            uint32_t off = (wm * 64 + mf * 16) * ROWB + kb + aoff;
            uint32_t af[4];
            ldsm4(af, sA + off);
#pragma unroll
            for (int nf = 0; nf < 8; nf++)
                mma16816(acc[mf][nf], af, bf + nf * 2);
        }
    }
}

// 3-stage circular pipeline, one __syncthreads per stage
__device__ __forceinline__ void gemm_mainloop(
    const __half* gA, const __half* gB,
    size_t Ks, int T, uint32_t smem_b, int tid, float acc[4][8][4])
{
    const int lane = tid & 31, wid = tid >> 5;
    const int wm = wid & 1, wn = wid >> 1;
    const uint32_t aoff = (uint32_t)((lane & 15) * ROWB + ((lane & 16) ? 16 : 0));
    const uint32_t boff = (uint32_t)(((lane & 7) + ((lane & 16) ? 8 : 0)) * ROWB
                                     + ((lane & 8) ? 16 : 0));
#pragma unroll
    for (int mf = 0; mf < 4; mf++)
#pragma unroll
        for (int nf = 0; nf < 8; nf++)
#pragma unroll
            for (int e = 0; e < 4; e++) acc[mf][nf][e] = 0.f;

    load_stage(gA, gB, Ks, 0, smem_b, tid);
    CP_COMMIT();
    load_stage(gA, gB, Ks, KT, smem_b + STAGE_B, tid);
    CP_COMMIT();

    int s_cur = 0, s_nxt = 2;   // buffer indices mod 3
    for (int t = 0; t < T; t++) {
        if (t == T - 1) { CP_WAIT(0); } else { CP_WAIT(1); }
        __syncthreads();
        if (t + 2 < T) {
            load_stage(gA, gB, Ks, (t + 2) * KT, smem_b + s_nxt * STAGE_B, tid);
            CP_COMMIT();
        }
        compute_stage(smem_b + s_cur * STAGE_B, wm, wn, aoff, boff, acc);
        s_cur = (s_cur == 2) ? 0 : s_cur + 1;
        s_nxt = (s_nxt == 2) ? 0 : s_nxt + 1;
    }
}

// ---------------------------------------------------------------------------
// quant_x: x -> fp16, plus 0.5*row-sum (exact fp32) for the centering correction
// ---------------------------------------------------------------------------
__global__ __launch_bounds__(256) void quant_x(const float* __restrict__ x) {
    const int w = blockIdx.x * 8 + (threadIdx.x >> 5);
    const int lane = threadIdx.x & 31;
    const float4* row = (const float4*)(x + (size_t)w * Ddim);
    float s = 0.f;
#pragma unroll
    for (int i = 0; i < 8; i++) {
        float4 v = row[lane + 32 * i];
        s += (v.x + v.y) + (v.z + v.w);
        __half2 h01 = __floats2half2_rn(v.x, v.y);
        __half2 h23 = __floats2half2_rn(v.z, v.w);
        __half2* o = (__half2*)(g_x + (size_t)w * Ddim + (lane + 32 * i) * 4);
        o[0] = h01; o[1] = h23;
    }
#pragma unroll
    for (int o = 16; o > 0; o >>= 1) s += __shfl_xor_sync(0xFFFFFFFFu, s, o);
    if (lane == 0) g_rs[w] = 0.5f * s;
}
// quant_p: (proto - 0.5) -> fp16, row-major and transposed
__global__ __launch_bounds__(256) void quant_p(const float* __restrict__ proto) {
    int idx = blockIdx.x * 256 + threadIdx.x;
    int p = idx / Ddim, d = idx % Ddim;
    __half h = __float2half_rn(proto[idx] - 0.5f);
    g_p[idx] = h;
    g_pt[(size_t)d * Pdim + p] = h;
}

// ---------------------------------------------------------------------------
// K1: Z^T[b][n][p] = x.(proto-0.5)^T + 0.5*rowsum(x) + gumbel.  M=n, N=p, K=d.
// ---------------------------------------------------------------------------
__global__ __launch_bounds__(128, 2) void k1_logits(const float* __restrict__ u) {
    extern __shared__ char smem[];
    const uint32_t smem_b = smem_u32_of(smem);
    const int tid = threadIdx.x, lane = tid & 31, wid = tid >> 5;
    const int wm = wid & 1, wn = wid >> 1;
    const int bn = blockIdx.x, bp = blockIdx.y, b = blockIdx.z;

    float acc[4][8][4];
    gemm_mainloop(g_x + ((size_t)b * Ndim + bn * 128) * Ddim,
                  g_p + (size_t)(bp * 128) * Ddim,
                  (size_t)Ddim, Ddim / KT, smem_b, tid, acc);

    // stage u tile [p0..p0+127][n0..n0+127] into smem (stride 132 floats)
    __syncthreads();
    float* u_s = (float*)smem;
    const float* ug = u + ((size_t)b * Pdim + (size_t)bp * 128) * Ndim + bn * 128;
#pragma unroll
    for (int j = 0; j < 32; j++) {
        int idx = tid + j * 128;        // 0..4095 float4s
        int row = idx >> 5, c4 = idx & 31;
        float4 v = *(const float4*)(ug + (size_t)row * Ndim + c4 * 4);
        *(float4*)(u_s + row * 132 + c4 * 4) = v;
    }
    __syncthreads();

    const int gID = lane >> 2, tg = lane & 3;
#pragma unroll
    for (int mf = 0; mf < 4; mf++) {
#pragma unroll
        for (int r2 = 0; r2 < 2; r2++) {
            const int nl = wm * 64 + mf * 16 + gID + r2 * 8;
            const float rsv = g_rs[(size_t)b * Ndim + bn * 128 + nl];
            const size_t rowbase = ((size_t)b * Ndim + bn * 128 + nl) * Pdim + bp * 128;
#pragma unroll
            for (int nf = 0; nf < 8; nf++) {
                const int pl = wn * 64 + nf * 8 + tg * 2;
                float u0 = u_s[pl * 132 + nl];
                float u1 = u_s[(pl + 1) * 132 + nl];
                float2 z;
                z.x = acc[mf][nf][r2 * 2 + 0] + rsv - __logf(-__logf(u0));
                z.y = acc[mf][nf][r2 * 2 + 1] + rsv - __logf(-__logf(u1));
                *(float2*)&g_ZT[rowbase + pl] = z;
            }
        }
    }
}

// ---------------------------------------------------------------------------
// K2: warp-per-(b,n) softmax over p; emit fp16 exp, 1/sum over QUANTIZED values
// ---------------------------------------------------------------------------
__global__ __launch_bounds__(256) void k2_softmax() {
    int wid = threadIdx.x >> 5, lane = threadIdx.x & 31;
    int n = blockIdx.x * 8 + wid, b = blockIdx.y;
    size_t rb = ((size_t)b * Ndim + n) * Pdim;
    const float4* row = (const float4*)(g_ZT + rb);
    float m = -3.4e38f;
#pragma unroll
    for (int i = 0; i < 16; i++) {
        float4 v = row[lane + 32 * i];
        m = fmaxf(m, fmaxf(fmaxf(v.x, v.y), fmaxf(v.z, v.w)));
    }
#pragma unroll
    for (int o = 16; o > 0; o >>= 1) m = fmaxf(m, __shfl_xor_sync(0xFFFFFFFFu, m, o));
    float s = 0.f;
    __half2* oa = (__half2*)(g_a + rb);
#pragma unroll 4
    for (int i = 0; i < 16; i++) {
        int i4 = lane + 32 * i;
        float4 v = row[i4];
        __half2 h01 = __floats2half2_rn(__expf(v.x - m), __expf(v.y - m));
        __half2 h23 = __floats2half2_rn(__expf(v.z - m), __expf(v.w - m));
        float2 f01 = __half22float2(h01), f23 = __half22float2(h23);
        s += (f01.x + f01.y) + (f23.x + f23.y);
        oa[i4 * 2 + 0] = h01;
        oa[i4 * 2 + 1] = h23;
    }
#pragma unroll
    for (int o = 16; o > 0; o >>= 1) s += __shfl_xor_sync(0xFFFFFFFFu, s, o);
    if (lane == 0) g_inv[(size_t)b * Ndim + n] = 1.0f / s;
}

// ---------------------------------------------------------------------------
// K3: out[b][n][d] = inv[b][n] * sum_p a[n][p] (proto-0.5)^T[d][p] + 0.5
// ---------------------------------------------------------------------------
__global__ __launch_bounds__(128, 2) void k3_combine(float* __restrict__ out) {
    extern __shared__ char smem[];
    const uint32_t smem_b = smem_u32_of(smem);
    const int tid = threadIdx.x, lane = tid & 31, wid = tid >> 5;
    const int wm = wid & 1, wn = wid >> 1;
    const int dt = blockIdx.x, nt = blockIdx.y, b = blockIdx.z;

    float acc[4][8][4];
    gemm_mainloop(g_a + ((size_t)b * Ndim + nt * 128) * Pdim,
                  g_pt + (size_t)(dt * 128) * Pdim,
                  (size_t)Pdim, Pdim / KT, smem_b, tid, acc);

    const int gID = lane >> 2, tg = lane & 3;
#pragma unroll
    for (int mf = 0; mf < 4; mf++) {
#pragma unroll
        for (int r2 = 0; r2 < 2; r2++) {
            const int nl = wm * 64 + mf * 16 + gID + r2 * 8;
            const int n_g = nt * 128 + nl;
            const float sc = g_inv[(size_t)b * Ndim + n_g];
            const size_t rowbase = ((size_t)b * Ndim + n_g) * Ddim + dt * 128;
#pragma unroll
            for (int nf = 0; nf < 8; nf++) {
                const int dl = wn * 64 + nf * 8 + tg * 2;
                float2 o;
                o.x = acc[mf][nf][r2 * 2 + 0] * sc + 0.5f;
                o.y = acc[mf][nf][r2 * 2 + 1] * sc + 0.5f;
                *(float2*)&out[rowbase + dl] = o;
            }
        }
    }
}

// ---------------------------------------------------------------------------
extern "C" void kernel_launch(void* const* d_in, const int* in_sizes, int n_in,
                              void* d_out, int out_size)
{
    (void)in_sizes; (void)n_in; (void)out_size;
    const float* x     = (const float*)d_in[0];  // [B, N, D]
    const float* u     = (const float*)d_in[1];  // [B, P, N]
    const float* proto = (const float*)d_in[2];  // [P, D]
    float* out = (float*)d_out;                  // [B, N, D]

    cudaFuncSetAttribute(k1_logits, cudaFuncAttributeMaxDynamicSharedMemorySize, DYN_SMEM);
    cudaFuncSetAttribute(k3_combine, cudaFuncAttributeMaxDynamicSharedMemorySize, DYN_SMEM);

    quant_x<<<(Bdim * Ndim) / 8, 256>>>(x);
    quant_p<<<(Pdim * Ddim) / 256, 256>>>(proto);

    dim3 g1(Ndim / 128, Pdim / 128, Bdim);
    k1_logits<<<g1, 128, DYN_SMEM>>>(u);

    dim3 g2(Ndim / 8, Bdim);
    k2_softmax<<<g2, 256>>>();

    dim3 g3(Ddim / 128, Ndim / 128, Bdim);
    k3_combine<<<g3, 128, DYN_SMEM>>>(out);
}

// round 9
// speedup vs baseline: 1.0629x; 1.0629x over previous
#include <cuda_runtime.h>
#include <cuda_fp16.h>
#include <cstdint>

#define Bdim 16
#define Ndim 2048
#define Ddim 1024
#define Pdim 2048

// ---------------- device scratch (static; allocation-free rule) ----------------
__device__ __align__(256) __half g_x[(size_t)Bdim * Ndim * Ddim];    // x fp16 [b][n][d]
__device__ __align__(256) __half g_p[(size_t)Pdim * Ddim];           // (proto-0.5) [p][d]
__device__ __align__(256) float  g_ZT[(size_t)Bdim * Ndim * Pdim];   // Z^T [b][n][p]
__device__ __align__(256) uint2  g_list[(size_t)Bdim * Ndim * Pdim]; // (p, w) survivors
__device__ __align__(256) int    g_cnt[(size_t)Bdim * Ndim];         // survivors per (b,n)
__device__ __align__(256) float  g_rs[(size_t)Bdim * Ndim];          // 0.5 * row-sum of x
__device__ __align__(256) float  g_inv[(size_t)Bdim * Ndim];         // 1/sum_exp (full)

// ---------------- baseline-PTX helpers (sm_80-class only) ----------------------
__device__ __forceinline__ uint32_t smem_u32_of(const void* p) {
    uint32_t a;
    asm("{ .reg .u64 t; cvta.to.shared.u64 t, %1; cvt.u32.u64 %0, t; }" : "=r"(a) : "l"(p));
    return a;
}
__device__ __forceinline__ void cpasync16(uint32_t s, const void* g) {
    asm volatile("cp.async.cg.shared.global [%0], [%1], 16;" :: "r"(s), "l"(g));
}
#define CP_COMMIT() asm volatile("cp.async.commit_group;")
#define CP_WAIT(n)  asm volatile("cp.async.wait_group %0;" :: "n"(n))

__device__ __forceinline__ void ldsm4(uint32_t* r, uint32_t addr) {
    asm volatile("ldmatrix.sync.aligned.m8n8.x4.shared.b16 {%0,%1,%2,%3}, [%4];"
                 : "=r"(r[0]), "=r"(r[1]), "=r"(r[2]), "=r"(r[3]) : "r"(addr));
}
__device__ __forceinline__ void mma16816(float* c, const uint32_t* a, const uint32_t* b) {
    asm volatile("mma.sync.aligned.m16n8k16.row.col.f32.f16.f16.f32 "
                 "{%0,%1,%2,%3}, {%4,%5,%6,%7}, {%8,%9}, {%0,%1,%2,%3};"
                 : "+f"(c[0]), "+f"(c[1]), "+f"(c[2]), "+f"(c[3])
                 : "r"(a[0]), "r"(a[1]), "r"(a[2]), "r"(a[3]), "r"(b[0]), "r"(b[1]));
}

// ---------------- tiling constants (R7 proven config) ----------------
static constexpr int KT = 64;                 // fp16 k per stage (128 data bytes/row)
static constexpr int ROWB = 144;              // padded smem row bytes (128 + 16)
static constexpr int TILE_B = 128 * ROWB;     // 18432 per operand tile
static constexpr int STAGE_B = 2 * TILE_B;    // A, B = 36864
static constexpr int NSTG = 3;                // circular pipeline depth
static constexpr int DYN_SMEM = NSTG * STAGE_B;   // 110592

static constexpr float THR = 1e-7f;           // survivor threshold on exp(z - max)

// load one stage (2 tiles x 128 rows x 128B), 8 cp.async per thread (256 thr)
__device__ __forceinline__ void load_stage(
    const __half* gA, const __half* gB,
    size_t Ks, int k0, uint32_t sbase, int tid)
{
    const __half* G[2] = {gA, gB};
#pragma unroll
    for (int j = 0; j < 8; j++) {
        const int idx = tid + j * 256;        // 0..2047
        const int tile = idx >> 10;
        const int c = idx & 1023;
        const int row = c >> 3, q = c & 7;
        cpasync16(sbase + tile * TILE_B + row * ROWB + q * 16,
                  G[tile] + (size_t)row * Ks + k0 + q * 8);
    }
}

// compute one k64 stage: 4 k16-steps x (4 m-frags x 4 n-frags)
__device__ __forceinline__ void compute_stage(
    uint32_t sbase, int wm, int wn, uint32_t aoff, uint32_t boff,
    float acc[4][4][4])
{
    const uint32_t sA = sbase;
    const uint32_t sB = sbase + TILE_B;
#pragma unroll
    for (int ks = 0; ks < 4; ks++) {
        const uint32_t kb = ks * 32;
        uint32_t bf[8];
#pragma unroll
        for (int f = 0; f < 2; f++) {
            uint32_t off = (wn * 32 + f * 16) * ROWB + kb + boff;
            ldsm4(bf + f * 4, sB + off);
        }
#pragma unroll
        for (int mf = 0; mf < 4; mf++) {
            uint32_t off = (wm * 64 + mf * 16) * ROWB + kb + aoff;
            uint32_t af[4];
            ldsm4(af, sA + off);
#pragma unroll
            for (int nf = 0; nf < 4; nf++)
                mma16816(acc[mf][nf], af, bf + nf * 2);
        }
    }
}

// 3-stage circular pipeline, one __syncthreads per stage
__device__ __forceinline__ void gemm_mainloop(
    const __half* gA, const __half* gB,
    size_t Ks, int T, uint32_t smem_b, int tid, float acc[4][4][4])
{
    const int lane = tid & 31, wid = tid >> 5;
    const int wm = wid & 1, wn = wid >> 1;
    const uint32_t aoff = (uint32_t)((lane & 15) * ROWB + ((lane & 16) ? 16 : 0));
    const uint32_t boff = (uint32_t)(((lane & 7) + ((lane & 16) ? 8 : 0)) * ROWB
                                     + ((lane & 8) ? 16 : 0));
#pragma unroll
    for (int mf = 0; mf < 4; mf++)
#pragma unroll
        for (int nf = 0; nf < 4; nf++)
#pragma unroll
            for (int e = 0; e < 4; e++) acc[mf][nf][e] = 0.f;

    load_stage(gA, gB, Ks, 0, smem_b, tid);
    CP_COMMIT();
    load_stage(gA, gB, Ks, KT, smem_b + STAGE_B, tid);
    CP_COMMIT();

    int s_cur = 0, s_nxt = 2;
    for (int t = 0; t < T; t++) {
        if (t == T - 1) { CP_WAIT(0); } else { CP_WAIT(1); }
        __syncthreads();
        if (t + 2 < T) {
            load_stage(gA, gB, Ks, (t + 2) * KT, smem_b + s_nxt * STAGE_B, tid);
            CP_COMMIT();
        }
        compute_stage(smem_b + s_cur * STAGE_B, wm, wn, aoff, boff, acc);
        s_cur = (s_cur == 2) ? 0 : s_cur + 1;
        s_nxt = (s_nxt == 2) ? 0 : s_nxt + 1;
    }
}

// ---------------------------------------------------------------------------
// quant_x: x -> fp16, plus 0.5*row-sum (exact fp32) for the centering correction
// ---------------------------------------------------------------------------
__global__ __launch_bounds__(256) void quant_x(const float* __restrict__ x) {
    const int w = blockIdx.x * 8 + (threadIdx.x >> 5);
    const int lane = threadIdx.x & 31;
    const float4* row = (const float4*)(x + (size_t)w * Ddim);
    float s = 0.f;
#pragma unroll
    for (int i = 0; i < 8; i++) {
        float4 v = row[lane + 32 * i];
        s += (v.x + v.y) + (v.z + v.w);
        __half2 h01 = __floats2half2_rn(v.x, v.y);
        __half2 h23 = __floats2half2_rn(v.z, v.w);
        __half2* o = (__half2*)(g_x + (size_t)w * Ddim + (lane + 32 * i) * 4);
        o[0] = h01; o[1] = h23;
    }
#pragma unroll
    for (int o = 16; o > 0; o >>= 1) s += __shfl_xor_sync(0xFFFFFFFFu, s, o);
    if (lane == 0) g_rs[w] = 0.5f * s;
}
// quant_p: (proto - 0.5) -> fp16 row-major only (sparse k3 reads rows)
__global__ __launch_bounds__(256) void quant_p(const float* __restrict__ proto) {
    int idx = blockIdx.x * 256 + threadIdx.x;
    g_p[idx] = __float2half_rn(proto[idx] - 0.5f);
}

// ---------------------------------------------------------------------------
// K1: Z^T[b][n][p] = x.(proto-0.5)^T + 0.5*rowsum(x) + gumbel.  (unchanged R7)
// ---------------------------------------------------------------------------
__global__ __launch_bounds__(256, 2) void k1_logits(const float* __restrict__ u) {
    extern __shared__ char smem[];
    const uint32_t smem_b = smem_u32_of(smem);
    const int tid = threadIdx.x, lane = tid & 31, wid = tid >> 5;
    const int wm = wid & 1, wn = wid >> 1;
    const int bn = blockIdx.x, bp = blockIdx.y, b = blockIdx.z;

    float acc[4][4][4];
    gemm_mainloop(g_x + ((size_t)b * Ndim + bn * 128) * Ddim,
                  g_p + (size_t)(bp * 128) * Ddim,
                  (size_t)Ddim, Ddim / KT, smem_b, tid, acc);

    __syncthreads();
    float* u_s = (float*)smem;
    const float* ug = u + ((size_t)b * Pdim + (size_t)bp * 128) * Ndim + bn * 128;
#pragma unroll
    for (int j = 0; j < 16; j++) {
        int idx = tid + j * 256;
        int row = idx >> 5, c4 = idx & 31;
        float4 v = *(const float4*)(ug + (size_t)row * Ndim + c4 * 4);
        *(float4*)(u_s + row * 132 + c4 * 4) = v;
    }
    __syncthreads();

    const int gID = lane >> 2, tg = lane & 3;
#pragma unroll
    for (int mf = 0; mf < 4; mf++) {
#pragma unroll
        for (int r2 = 0; r2 < 2; r2++) {
            const int nl = wm * 64 + mf * 16 + gID + r2 * 8;
            const float rsv = g_rs[(size_t)b * Ndim + bn * 128 + nl];
            const size_t rowbase = ((size_t)b * Ndim + bn * 128 + nl) * Pdim + bp * 128;
#pragma unroll
            for (int nf = 0; nf < 4; nf++) {
                const int pl = wn * 32 + nf * 8 + tg * 2;
                float u0 = u_s[pl * 132 + nl];
                float u1 = u_s[(pl + 1) * 132 + nl];
                float2 z;
                z.x = acc[mf][nf][r2 * 2 + 0] + rsv - __logf(-__logf(u0));
                z.y = acc[mf][nf][r2 * 2 + 1] + rsv - __logf(-__logf(u1));
                *(float2*)&g_ZT[rowbase + pl] = z;
            }
        }
    }
}

// ---------------------------------------------------------------------------
// K2: warp-per-(b,n) softmax over p; deterministic ballot-compaction of
// survivors (w > THR) into g_list as (p, w_fp32); 1/sum over the FULL sum.
// ---------------------------------------------------------------------------
__global__ __launch_bounds__(256) void k2_softmax() {
    int wid = threadIdx.x >> 5, lane = threadIdx.x & 31;
    int n = blockIdx.x * 8 + wid, b = blockIdx.y;
    size_t rb = ((size_t)b * Ndim + n) * Pdim;
    const float4* row = (const float4*)(g_ZT + rb);
    float m = -3.4e38f;
#pragma unroll
    for (int i = 0; i < 16; i++) {
        float4 v = row[lane + 32 * i];
        m = fmaxf(m, fmaxf(fmaxf(v.x, v.y), fmaxf(v.z, v.w)));
    }
#pragma unroll
    for (int o = 16; o > 0; o >>= 1) m = fmaxf(m, __shfl_xor_sync(0xFFFFFFFFu, m, o));

    float s = 0.f;
    uint32_t cnt = 0;
    uint2* lst = g_list + rb;
#pragma unroll 2
    for (int i = 0; i < 16; i++) {
        int i4 = lane + 32 * i;
        float4 v = row[i4];
        float w4[4];
        w4[0] = __expf(v.x - m); w4[1] = __expf(v.y - m);
        w4[2] = __expf(v.z - m); w4[3] = __expf(v.w - m);
        s += (w4[0] + w4[1]) + (w4[2] + w4[3]);
#pragma unroll
        for (int j = 0; j < 4; j++) {
            bool keep = (w4[j] > THR);
            unsigned msk = __ballot_sync(0xFFFFFFFFu, keep);
            if (keep) {
                int off = __popc(msk & ((1u << lane) - 1u));
                lst[cnt + off] = make_uint2((unsigned)(i4 * 4 + j),
                                            __float_as_uint(w4[j]));
            }
            cnt += (uint32_t)__popc(msk);
        }
    }
#pragma unroll
    for (int o = 16; o > 0; o >>= 1) s += __shfl_xor_sync(0xFFFFFFFFu, s, o);
    if (lane == 0) {
        g_inv[(size_t)b * Ndim + n] = 1.0f / s;
        g_cnt[(size_t)b * Ndim + n] = (int)cnt;
    }
}

// ---------------------------------------------------------------------------
// K3 sparse: warp-per-(b,n). out[b][n][d] = inv * sum_j w_j * protoC[p_j][d] + 0.5
// proto rows are 2KB fp16, L2-resident (g_p = 4MB). Coalesced row reads.
// acc layout: acc[q*8+r] holds d = (lane + 32q)*8 + r.
// ---------------------------------------------------------------------------
__global__ __launch_bounds__(256) void k3_sparse(float* __restrict__ out) {
    int wid = threadIdx.x >> 5, lane = threadIdx.x & 31;
    int n = blockIdx.x * 8 + wid, b = blockIdx.y;
    size_t rn = (size_t)b * Ndim + n;
    const uint2* lst = g_list + rn * Pdim;
    const int L = g_cnt[rn];
    const float inv = g_inv[rn];

    float acc[32];
#pragma unroll
    for (int k = 0; k < 32; k++) acc[k] = 0.f;

#pragma unroll 2
    for (int j = 0; j < L; j++) {
        uint2 e = lst[j];                       // broadcast load (same addr all lanes)
        float w = __uint_as_float(e.y);
        const uint4* prow = (const uint4*)(g_p + (size_t)e.x * Ddim);
#pragma unroll
        for (int q = 0; q < 4; q++) {
            uint4 pk = prow[lane + 32 * q];     // 8 fp16, coalesced
            const __half2* h = (const __half2*)&pk;
#pragma unroll
            for (int t = 0; t < 4; t++) {
                float2 f = __half22float2(h[t]);
                acc[q * 8 + t * 2 + 0] = fmaf(w, f.x, acc[q * 8 + t * 2 + 0]);
                acc[q * 8 + t * 2 + 1] = fmaf(w, f.y, acc[q * 8 + t * 2 + 1]);
            }
        }
    }

    float* orow = out + rn * Ddim;
#pragma unroll
    for (int q = 0; q < 4; q++) {
        int d0 = (lane + 32 * q) * 8;
#pragma unroll
        for (int t = 0; t < 8; t++)
            orow[d0 + t] = acc[q * 8 + t] * inv + 0.5f;
    }
}

// ---------------------------------------------------------------------------
extern "C" void kernel_launch(void* const* d_in, const int* in_sizes, int n_in,
                              void* d_out, int out_size)
{
    (void)in_sizes; (void)n_in; (void)out_size;
    const float* x     = (const float*)d_in[0];  // [B, N, D]
    const float* u     = (const float*)d_in[1];  // [B, P, N]
    const float* proto = (const float*)d_in[2];  // [P, D]
    float* out = (float*)d_out;                  // [B, N, D]

    cudaFuncSetAttribute(k1_logits, cudaFuncAttributeMaxDynamicSharedMemorySize, DYN_SMEM);

    quant_x<<<(Bdim * Ndim) / 8, 256>>>(x);
    quant_p<<<(Pdim * Ddim) / 256, 256>>>(proto);

    dim3 g1(Ndim / 128, Pdim / 128, Bdim);
    k1_logits<<<g1, 256, DYN_SMEM>>>(u);

    dim3 g2(Ndim / 8, Bdim);
    k2_softmax<<<g2, 256>>>();

    dim3 g3(Ndim / 8, Bdim);
    k3_sparse<<<g3, 256>>>(out);
}

// round 10
// speedup vs baseline: 1.4880x; 1.3999x over previous
#include <cuda_runtime.h>
#include <cuda_fp16.h>
#include <cstdint>

#define Bdim 16
#define Ndim 2048
#define Ddim 1024
#define Pdim 2048

// ---------------- device scratch (static; allocation-free rule) ----------------
__device__ __align__(256) __half g_x[(size_t)Bdim * Ndim * Ddim];    // x fp16 [b][n][d]
__device__ __align__(256) __half g_p[(size_t)Pdim * Ddim];           // (proto-0.5) [p][d]
__device__ __align__(256) float  g_ZT[(size_t)Bdim * Ndim * Pdim];   // Z^T [b][n][p]
__device__ __align__(256) uint2  g_list[(size_t)Bdim * Ndim * Pdim]; // (p, w) survivors
__device__ __align__(256) int    g_cnt[(size_t)Bdim * Ndim];         // survivors per (b,n)
__device__ __align__(256) float  g_rs[(size_t)Bdim * Ndim];          // 0.5 * row-sum of x
__device__ __align__(256) float  g_inv[(size_t)Bdim * Ndim];         // 1/sum_exp (full)

// ---------------- baseline-PTX helpers (sm_80-class only) ----------------------
__device__ __forceinline__ uint32_t smem_u32_of(const void* p) {
    uint32_t a;
    asm("{ .reg .u64 t; cvta.to.shared.u64 t, %1; cvt.u32.u64 %0, t; }" : "=r"(a) : "l"(p));
    return a;
}
__device__ __forceinline__ void cpasync16(uint32_t s, const void* g) {
    asm volatile("cp.async.cg.shared.global [%0], [%1], 16;" :: "r"(s), "l"(g));
}
#define CP_COMMIT() asm volatile("cp.async.commit_group;")
#define CP_WAIT(n)  asm volatile("cp.async.wait_group %0;" :: "n"(n))

__device__ __forceinline__ void ldsm4(uint32_t* r, uint32_t addr) {
    asm volatile("ldmatrix.sync.aligned.m8n8.x4.shared.b16 {%0,%1,%2,%3}, [%4];"
                 : "=r"(r[0]), "=r"(r[1]), "=r"(r[2]), "=r"(r[3]) : "r"(addr));
}
__device__ __forceinline__ void mma16816(float* c, const uint32_t* a, const uint32_t* b) {
    asm volatile("mma.sync.aligned.m16n8k16.row.col.f32.f16.f16.f32 "
                 "{%0,%1,%2,%3}, {%4,%5,%6,%7}, {%8,%9}, {%0,%1,%2,%3};"
                 : "+f"(c[0]), "+f"(c[1]), "+f"(c[2]), "+f"(c[3])
                 : "r"(a[0]), "r"(a[1]), "r"(a[2]), "r"(a[3]), "r"(b[0]), "r"(b[1]));
}

// ---------------- tiling constants (R7 proven config) ----------------
static constexpr int KT = 64;                 // fp16 k per stage (128 data bytes/row)
static constexpr int ROWB = 144;              // padded smem row bytes (128 + 16)
static constexpr int TILE_B = 128 * ROWB;     // 18432 per operand tile
static constexpr int STAGE_B = 2 * TILE_B;    // A, B = 36864
static constexpr int NSTG = 3;                // circular pipeline depth
static constexpr int DYN_SMEM = NSTG * STAGE_B;   // 110592

static constexpr float THR = 1e-5f;           // survivor threshold on exp(z - max)

// load one stage (2 tiles x 128 rows x 128B), 8 cp.async per thread (256 thr)
__device__ __forceinline__ void load_stage(
    const __half* gA, const __half* gB,
    size_t Ks, int k0, uint32_t sbase, int tid)
{
    const __half* G[2] = {gA, gB};
#pragma unroll
    for (int j = 0; j < 8; j++) {
        const int idx = tid + j * 256;        // 0..2047
        const int tile = idx >> 10;
        const int c = idx & 1023;
        const int row = c >> 3, q = c & 7;
        cpasync16(sbase + tile * TILE_B + row * ROWB + q * 16,
                  G[tile] + (size_t)row * Ks + k0 + q * 8);
    }
}

// compute one k64 stage: 4 k16-steps x (4 m-frags x 4 n-frags)
__device__ __forceinline__ void compute_stage(
    uint32_t sbase, int wm, int wn, uint32_t aoff, uint32_t boff,
    float acc[4][4][4])
{
    const uint32_t sA = sbase;
    const uint32_t sB = sbase + TILE_B;
#pragma unroll
    for (int ks = 0; ks < 4; ks++) {
        const uint32_t kb = ks * 32;
        uint32_t bf[8];
#pragma unroll
        for (int f = 0; f < 2; f++) {
            uint32_t off = (wn * 32 + f * 16) * ROWB + kb + boff;
            ldsm4(bf + f * 4, sB + off);
        }
#pragma unroll
        for (int mf = 0; mf < 4; mf++) {
            uint32_t off = (wm * 64 + mf * 16) * ROWB + kb + aoff;
            uint32_t af[4];
            ldsm4(af, sA + off);
#pragma unroll
            for (int nf = 0; nf < 4; nf++)
                mma16816(acc[mf][nf], af, bf + nf * 2);
        }
    }
}

// 3-stage circular pipeline, one __syncthreads per stage
__device__ __forceinline__ void gemm_mainloop(
    const __half* gA, const __half* gB,
    size_t Ks, int T, uint32_t smem_b, int tid, float acc[4][4][4])
{
    const int lane = tid & 31, wid = tid >> 5;
    const int wm = wid & 1, wn = wid >> 1;
    const uint32_t aoff = (uint32_t)((lane & 15) * ROWB + ((lane & 16) ? 16 : 0));
    const uint32_t boff = (uint32_t)(((lane & 7) + ((lane & 16) ? 8 : 0)) * ROWB
                                     + ((lane & 8) ? 16 : 0));
#pragma unroll
    for (int mf = 0; mf < 4; mf++)
#pragma unroll
        for (int nf = 0; nf < 4; nf++)
#pragma unroll
            for (int e = 0; e < 4; e++) acc[mf][nf][e] = 0.f;

    load_stage(gA, gB, Ks, 0, smem_b, tid);
    CP_COMMIT();
    load_stage(gA, gB, Ks, KT, smem_b + STAGE_B, tid);
    CP_COMMIT();

    int s_cur = 0, s_nxt = 2;
    for (int t = 0; t < T; t++) {
        if (t == T - 1) { CP_WAIT(0); } else { CP_WAIT(1); }
        __syncthreads();
        if (t + 2 < T) {
            load_stage(gA, gB, Ks, (t + 2) * KT, smem_b + s_nxt * STAGE_B, tid);
            CP_COMMIT();
        }
        compute_stage(smem_b + s_cur * STAGE_B, wm, wn, aoff, boff, acc);
        s_cur = (s_cur == 2) ? 0 : s_cur + 1;
        s_nxt = (s_nxt == 2) ? 0 : s_nxt + 1;
    }
}

// ---------------------------------------------------------------------------
// quant_x: x -> fp16, plus 0.5*row-sum (exact fp32) for the centering correction
// ---------------------------------------------------------------------------
__global__ __launch_bounds__(256) void quant_x(const float* __restrict__ x) {
    const int w = blockIdx.x * 8 + (threadIdx.x >> 5);
    const int lane = threadIdx.x & 31;
    const float4* row = (const float4*)(x + (size_t)w * Ddim);
    float s = 0.f;
#pragma unroll
    for (int i = 0; i < 8; i++) {
        float4 v = row[lane + 32 * i];
        s += (v.x + v.y) + (v.z + v.w);
        __half2 h01 = __floats2half2_rn(v.x, v.y);
        __half2 h23 = __floats2half2_rn(v.z, v.w);
        __half2* o = (__half2*)(g_x + (size_t)w * Ddim + (lane + 32 * i) * 4);
        o[0] = h01; o[1] = h23;
    }
#pragma unroll
    for (int o = 16; o > 0; o >>= 1) s += __shfl_xor_sync(0xFFFFFFFFu, s, o);
    if (lane == 0) g_rs[w] = 0.5f * s;
}
// quant_p: (proto - 0.5) -> fp16 row-major (k1 B-operand and sparse k3 rows)
__global__ __launch_bounds__(256) void quant_p(const float* __restrict__ proto) {
    int idx = blockIdx.x * 256 + threadIdx.x;
    g_p[idx] = __float2half_rn(proto[idx] - 0.5f);
}

// ---------------------------------------------------------------------------
// K1: Z^T[b][n][p] = x.(proto-0.5)^T + 0.5*rowsum(x) + gumbel.  (R7 proven)
// ---------------------------------------------------------------------------
__global__ __launch_bounds__(256, 2) void k1_logits(const float* __restrict__ u) {
    extern __shared__ char smem[];
    const uint32_t smem_b = smem_u32_of(smem);
    const int tid = threadIdx.x, lane = tid & 31, wid = tid >> 5;
    const int wm = wid & 1, wn = wid >> 1;
    const int bn = blockIdx.x, bp = blockIdx.y, b = blockIdx.z;

    float acc[4][4][4];
    gemm_mainloop(g_x + ((size_t)b * Ndim + bn * 128) * Ddim,
                  g_p + (size_t)(bp * 128) * Ddim,
                  (size_t)Ddim, Ddim / KT, smem_b, tid, acc);

    __syncthreads();
    float* u_s = (float*)smem;
    const float* ug = u + ((size_t)b * Pdim + (size_t)bp * 128) * Ndim + bn * 128;
#pragma unroll
    for (int j = 0; j < 16; j++) {
        int idx = tid + j * 256;
        int row = idx >> 5, c4 = idx & 31;
        float4 v = *(const float4*)(ug + (size_t)row * Ndim + c4 * 4);
        *(float4*)(u_s + row * 132 + c4 * 4) = v;
    }
    __syncthreads();

    const int gID = lane >> 2, tg = lane & 3;
#pragma unroll
    for (int mf = 0; mf < 4; mf++) {
#pragma unroll
        for (int r2 = 0; r2 < 2; r2++) {
            const int nl = wm * 64 + mf * 16 + gID + r2 * 8;
            const float rsv = g_rs[(size_t)b * Ndim + bn * 128 + nl];
            const size_t rowbase = ((size_t)b * Ndim + bn * 128 + nl) * Pdim + bp * 128;
#pragma unroll
            for (int nf = 0; nf < 4; nf++) {
                const int pl = wn * 32 + nf * 8 + tg * 2;
                float u0 = u_s[pl * 132 + nl];
                float u1 = u_s[(pl + 1) * 132 + nl];
                float2 z;
                z.x = acc[mf][nf][r2 * 2 + 0] + rsv - __logf(-__logf(u0));
                z.y = acc[mf][nf][r2 * 2 + 1] + rsv - __logf(-__logf(u1));
                *(float2*)&g_ZT[rowbase + pl] = z;
            }
        }
    }
}

// ---------------------------------------------------------------------------
// K2: warp-per-(b,n) softmax over p; deterministic ballot-compaction of
// survivors (w > THR) into g_list as (p, w_fp32); 1/sum over the FULL sum.
// ---------------------------------------------------------------------------
__global__ __launch_bounds__(256) void k2_softmax() {
    int wid = threadIdx.x >> 5, lane = threadIdx.x & 31;
    int n = blockIdx.x * 8 + wid, b = blockIdx.y;
    size_t rb = ((size_t)b * Ndim + n) * Pdim;
    const float4* row = (const float4*)(g_ZT + rb);
    float m = -3.4e38f;
#pragma unroll
    for (int i = 0; i < 16; i++) {
        float4 v = row[lane + 32 * i];
        m = fmaxf(m, fmaxf(fmaxf(v.x, v.y), fmaxf(v.z, v.w)));
    }
#pragma unroll
    for (int o = 16; o > 0; o >>= 1) m = fmaxf(m, __shfl_xor_sync(0xFFFFFFFFu, m, o));

    float s = 0.f;
    uint32_t cnt = 0;
    uint2* lst = g_list + rb;
#pragma unroll 2
    for (int i = 0; i < 16; i++) {
        int i4 = lane + 32 * i;
        float4 v = row[i4];
        float w4[4];
        w4[0] = __expf(v.x - m); w4[1] = __expf(v.y - m);
        w4[2] = __expf(v.z - m); w4[3] = __expf(v.w - m);
        s += (w4[0] + w4[1]) + (w4[2] + w4[3]);
#pragma unroll
        for (int j = 0; j < 4; j++) {
            bool keep = (w4[j] > THR);
            unsigned msk = __ballot_sync(0xFFFFFFFFu, keep);
            if (keep) {
                int off = __popc(msk & ((1u << lane) - 1u));
                lst[cnt + off] = make_uint2((unsigned)(i4 * 4 + j),
                                            __float_as_uint(w4[j]));
            }
            cnt += (uint32_t)__popc(msk);
        }
    }
#pragma unroll
    for (int o = 16; o > 0; o >>= 1) s += __shfl_xor_sync(0xFFFFFFFFu, s, o);
    if (lane == 0) {
        g_inv[(size_t)b * Ndim + n] = 1.0f / s;
        g_cnt[(size_t)b * Ndim + n] = (int)cnt;
    }
}

// ---------------------------------------------------------------------------
// K3 sparse: warp-per-(b,n). out[b][n][d] = inv * sum_j w_j * protoC[p_j][d] + 0.5
// proto rows are 2KB fp16 (g_p = 4MB, L2-resident). Iterations are independent
// except for the fp32 accumulators, so unroll-4 batches 4 entries' loads.
// ---------------------------------------------------------------------------
__global__ __launch_bounds__(256) void k3_sparse(float* __restrict__ out) {
    int wid = threadIdx.x >> 5, lane = threadIdx.x & 31;
    int n = blockIdx.x * 8 + wid, b = blockIdx.y;
    size_t rn = (size_t)b * Ndim + n;
    const uint2* __restrict__ lst = g_list + rn * Pdim;
    const int L = g_cnt[rn];
    const float inv = g_inv[rn];

    float acc[32];
#pragma unroll
    for (int k = 0; k < 32; k++) acc[k] = 0.f;

#pragma unroll 4
    for (int j = 0; j < L; j++) {
        uint2 e = lst[j];                       // broadcast load
        float w = __uint_as_float(e.y);
        const uint4* __restrict__ prow = (const uint4*)(g_p + (size_t)e.x * Ddim);
        uint4 pk[4];
#pragma unroll
        for (int q = 0; q < 4; q++) pk[q] = prow[lane + 32 * q];   // batched loads
#pragma unroll
        for (int q = 0; q < 4; q++) {
            const __half2* h = (const __half2*)&pk[q];
#pragma unroll
            for (int t = 0; t < 4; t++) {
                float2 f = __half22float2(h[t]);
                acc[q * 8 + t * 2 + 0] = fmaf(w, f.x, acc[q * 8 + t * 2 + 0]);
                acc[q * 8 + t * 2 + 1] = fmaf(w, f.y, acc[q * 8 + t * 2 + 1]);
            }
        }
    }

    float* orow = out + rn * Ddim;
#pragma unroll
    for (int q = 0; q < 4; q++) {
        int d0 = (lane + 32 * q) * 8;
        float4 o0, o1;
        o0.x = acc[q * 8 + 0] * inv + 0.5f; o0.y = acc[q * 8 + 1] * inv + 0.5f;
        o0.z = acc[q * 8 + 2] * inv + 0.5f; o0.w = acc[q * 8 + 3] * inv + 0.5f;
        o1.x = acc[q * 8 + 4] * inv + 0.5f; o1.y = acc[q * 8 + 5] * inv + 0.5f;
        o1.z = acc[q * 8 + 6] * inv + 0.5f; o1.w = acc[q * 8 + 7] * inv + 0.5f;
        *(float4*)(orow + d0) = o0;
        *(float4*)(orow + d0 + 4) = o1;
    }
}

// ---------------------------------------------------------------------------
extern "C" void kernel_launch(void* const* d_in, const int* in_sizes, int n_in,
                              void* d_out, int out_size)
{
    (void)in_sizes; (void)n_in; (void)out_size;
    const float* x     = (const float*)d_in[0];  // [B, N, D]
    const float* u     = (const float*)d_in[1];  // [B, P, N]
    const float* proto = (const float*)d_in[2];  // [P, D]
    float* out = (float*)d_out;                  // [B, N, D]

    cudaFuncSetAttribute(k1_logits, cudaFuncAttributeMaxDynamicSharedMemorySize, DYN_SMEM);

    quant_x<<<(Bdim * Ndim) / 8, 256>>>(x);
    quant_p<<<(Pdim * Ddim) / 256, 256>>>(proto);

    dim3 g1(Ndim / 128, Pdim / 128, Bdim);
    k1_logits<<<g1, 256, DYN_SMEM>>>(u);

    dim3 g2(Ndim / 8, Bdim);
    k2_softmax<<<g2, 256>>>();

    dim3 g3(Ndim / 8, Bdim);
    k3_sparse<<<g3, 256>>>(out);
}

// round 11
// speedup vs baseline: 1.7098x; 1.1491x over previous
#include <cuda_runtime.h>
#include <cuda_fp16.h>
#include <cstdint>

#define Bdim 16
#define Ndim 2048
#define Ddim 1024
#define Pdim 2048

// ---------------- device scratch (static; allocation-free rule) ----------------
__device__ __align__(256) __half g_x[(size_t)Bdim * Ndim * Ddim];    // x fp16 [b][n][d]
__device__ __align__(256) __half g_p[(size_t)Pdim * Ddim];           // (proto-0.5) [p][d]
__device__ __align__(256) float  g_ZT[(size_t)Bdim * Ndim * Pdim];   // Z^T [b][n][p]
__device__ __align__(256) uint2  g_list[(size_t)Bdim * Ndim * Pdim]; // (p, w) survivors
__device__ __align__(256) int    g_cnt[(size_t)Bdim * Ndim];         // survivors per (b,n)
__device__ __align__(256) float  g_rs[(size_t)Bdim * Ndim];          // 0.5 * row-sum of x
__device__ __align__(256) float  g_inv[(size_t)Bdim * Ndim];         // 1/sum_exp (full)

// ---------------- baseline-PTX helpers (sm_80-class only) ----------------------
__device__ __forceinline__ uint32_t smem_u32_of(const void* p) {
    uint32_t a;
    asm("{ .reg .u64 t; cvta.to.shared.u64 t, %1; cvt.u32.u64 %0, t; }" : "=r"(a) : "l"(p));
    return a;
}
__device__ __forceinline__ void cpasync16(uint32_t s, const void* g) {
    asm volatile("cp.async.cg.shared.global [%0], [%1], 16;" :: "r"(s), "l"(g));
}
#define CP_COMMIT() asm volatile("cp.async.commit_group;")
#define CP_WAIT(n)  asm volatile("cp.async.wait_group %0;" :: "n"(n))

__device__ __forceinline__ void ldsm4(uint32_t* r, uint32_t addr) {
    asm volatile("ldmatrix.sync.aligned.m8n8.x4.shared.b16 {%0,%1,%2,%3}, [%4];"
                 : "=r"(r[0]), "=r"(r[1]), "=r"(r[2]), "=r"(r[3]) : "r"(addr));
}
__device__ __forceinline__ void mma16816(float* c, const uint32_t* a, const uint32_t* b) {
    asm volatile("mma.sync.aligned.m16n8k16.row.col.f32.f16.f16.f32 "
                 "{%0,%1,%2,%3}, {%4,%5,%6,%7}, {%8,%9}, {%0,%1,%2,%3};"
                 : "+f"(c[0]), "+f"(c[1]), "+f"(c[2]), "+f"(c[3])
                 : "r"(a[0]), "r"(a[1]), "r"(a[2]), "r"(a[3]), "r"(b[0]), "r"(b[1]));
}

// ---------------- tiling constants (R7 proven config) ----------------
static constexpr int KT = 64;                 // fp16 k per stage (128 data bytes/row)
static constexpr int ROWB = 144;              // padded smem row bytes (128 + 16)
static constexpr int TILE_B = 128 * ROWB;     // 18432 per operand tile
static constexpr int STAGE_B = 2 * TILE_B;    // A, B = 36864
static constexpr int NSTG = 3;                // circular pipeline depth
static constexpr int DYN_SMEM = NSTG * STAGE_B;   // 110592

static constexpr float THR = 1e-4f;           // survivor threshold on exp(z - max)

// load one stage (2 tiles x 128 rows x 128B), 8 cp.async per thread (256 thr)
__device__ __forceinline__ void load_stage(
    const __half* gA, const __half* gB,
    size_t Ks, int k0, uint32_t sbase, int tid)
{
    const __half* G[2] = {gA, gB};
#pragma unroll
    for (int j = 0; j < 8; j++) {
        const int idx = tid + j * 256;        // 0..2047
        const int tile = idx >> 10;
        const int c = idx & 1023;
        const int row = c >> 3, q = c & 7;
        cpasync16(sbase + tile * TILE_B + row * ROWB + q * 16,
                  G[tile] + (size_t)row * Ks + k0 + q * 8);
    }
}

// compute one k64 stage: 4 k16-steps x (4 m-frags x 4 n-frags)
__device__ __forceinline__ void compute_stage(
    uint32_t sbase, int wm, int wn, uint32_t aoff, uint32_t boff,
    float acc[4][4][4])
{
    const uint32_t sA = sbase;
    const uint32_t sB = sbase + TILE_B;
#pragma unroll
    for (int ks = 0; ks < 4; ks++) {
        const uint32_t kb = ks * 32;
        uint32_t bf[8];
#pragma unroll
        for (int f = 0; f < 2; f++) {
            uint32_t off = (wn * 32 + f * 16) * ROWB + kb + boff;
            ldsm4(bf + f * 4, sB + off);
        }
#pragma unroll
        for (int mf = 0; mf < 4; mf++) {
            uint32_t off = (wm * 64 + mf * 16) * ROWB + kb + aoff;
            uint32_t af[4];
            ldsm4(af, sA + off);
#pragma unroll
            for (int nf = 0; nf < 4; nf++)
                mma16816(acc[mf][nf], af, bf + nf * 2);
        }
    }
}

// 3-stage circular pipeline, one __syncthreads per stage
__device__ __forceinline__ void gemm_mainloop(
    const __half* gA, const __half* gB,
    size_t Ks, int T, uint32_t smem_b, int tid, float acc[4][4][4])
{
    const int lane = tid & 31, wid = tid >> 5;
    const int wm = wid & 1, wn = wid >> 1;
    const uint32_t aoff = (uint32_t)((lane & 15) * ROWB + ((lane & 16) ? 16 : 0));
    const uint32_t boff = (uint32_t)(((lane & 7) + ((lane & 16) ? 8 : 0)) * ROWB
                                     + ((lane & 8) ? 16 : 0));
#pragma unroll
    for (int mf = 0; mf < 4; mf++)
#pragma unroll
        for (int nf = 0; nf < 4; nf++)
#pragma unroll
            for (int e = 0; e < 4; e++) acc[mf][nf][e] = 0.f;

    load_stage(gA, gB, Ks, 0, smem_b, tid);
    CP_COMMIT();
    load_stage(gA, gB, Ks, KT, smem_b + STAGE_B, tid);
    CP_COMMIT();

    int s_cur = 0, s_nxt = 2;
    for (int t = 0; t < T; t++) {
        if (t == T - 1) { CP_WAIT(0); } else { CP_WAIT(1); }
        __syncthreads();
        if (t + 2 < T) {
            load_stage(gA, gB, Ks, (t + 2) * KT, smem_b + s_nxt * STAGE_B, tid);
            CP_COMMIT();
        }
        compute_stage(smem_b + s_cur * STAGE_B, wm, wn, aoff, boff, acc);
        s_cur = (s_cur == 2) ? 0 : s_cur + 1;
        s_nxt = (s_nxt == 2) ? 0 : s_nxt + 1;
    }
}

// ---------------------------------------------------------------------------
// quant_x: x -> fp16, plus 0.5*row-sum (exact fp32) for the centering correction
// ---------------------------------------------------------------------------
__global__ __launch_bounds__(256) void quant_x(const float* __restrict__ x) {
    const int w = blockIdx.x * 8 + (threadIdx.x >> 5);
    const int lane = threadIdx.x & 31;
    const float4* row = (const float4*)(x + (size_t)w * Ddim);
    float s = 0.f;
#pragma unroll
    for (int i = 0; i < 8; i++) {
        float4 v = row[lane + 32 * i];
        s += (v.x + v.y) + (v.z + v.w);
        __half2 h01 = __floats2half2_rn(v.x, v.y);
        __half2 h23 = __floats2half2_rn(v.z, v.w);
        __half2* o = (__half2*)(g_x + (size_t)w * Ddim + (lane + 32 * i) * 4);
        o[0] = h01; o[1] = h23;
    }
#pragma unroll
    for (int o = 16; o > 0; o >>= 1) s += __shfl_xor_sync(0xFFFFFFFFu, s, o);
    if (lane == 0) g_rs[w] = 0.5f * s;
}
// quant_p: (proto - 0.5) -> fp16 row-major (k1 B-operand and sparse k3 rows)
__global__ __launch_bounds__(256) void quant_p(const float* __restrict__ proto) {
    int idx = blockIdx.x * 256 + threadIdx.x;
    g_p[idx] = __float2half_rn(proto[idx] - 0.5f);
}

// ---------------------------------------------------------------------------
// K1: Z^T[b][n][p] = x.(proto-0.5)^T + 0.5*rowsum(x) + gumbel.  (R7 proven)
// ---------------------------------------------------------------------------
__global__ __launch_bounds__(256, 2) void k1_logits(const float* __restrict__ u) {
    extern __shared__ char smem[];
    const uint32_t smem_b = smem_u32_of(smem);
    const int tid = threadIdx.x, lane = tid & 31, wid = tid >> 5;
    const int wm = wid & 1, wn = wid >> 1;
    const int bn = blockIdx.x, bp = blockIdx.y, b = blockIdx.z;

    float acc[4][4][4];
    gemm_mainloop(g_x + ((size_t)b * Ndim + bn * 128) * Ddim,
                  g_p + (size_t)(bp * 128) * Ddim,
                  (size_t)Ddim, Ddim / KT, smem_b, tid, acc);

    __syncthreads();
    float* u_s = (float*)smem;
    const float* ug = u + ((size_t)b * Pdim + (size_t)bp * 128) * Ndim + bn * 128;
#pragma unroll
    for (int j = 0; j < 16; j++) {
        int idx = tid + j * 256;
        int row = idx >> 5, c4 = idx & 31;
        float4 v = *(const float4*)(ug + (size_t)row * Ndim + c4 * 4);
        *(float4*)(u_s + row * 132 + c4 * 4) = v;
    }
    __syncthreads();

    const int gID = lane >> 2, tg = lane & 3;
#pragma unroll
    for (int mf = 0; mf < 4; mf++) {
#pragma unroll
        for (int r2 = 0; r2 < 2; r2++) {
            const int nl = wm * 64 + mf * 16 + gID + r2 * 8;
            const float rsv = g_rs[(size_t)b * Ndim + bn * 128 + nl];
            const size_t rowbase = ((size_t)b * Ndim + bn * 128 + nl) * Pdim + bp * 128;
#pragma unroll
            for (int nf = 0; nf < 4; nf++) {
                const int pl = wn * 32 + nf * 8 + tg * 2;
                float u0 = u_s[pl * 132 + nl];
                float u1 = u_s[(pl + 1) * 132 + nl];
                float2 z;
                z.x = acc[mf][nf][r2 * 2 + 0] + rsv - __logf(-__logf(u0));
                z.y = acc[mf][nf][r2 * 2 + 1] + rsv - __logf(-__logf(u1));
                *(float2*)&g_ZT[rowbase + pl] = z;
            }
        }
    }
}

// ---------------------------------------------------------------------------
// K2: warp-per-(b,n) softmax over p; deterministic ballot-compaction of
// survivors (w > THR) into g_list as (p, w_fp32); 1/sum over the FULL sum.
// ---------------------------------------------------------------------------
__global__ __launch_bounds__(256) void k2_softmax() {
    int wid = threadIdx.x >> 5, lane = threadIdx.x & 31;
    int n = blockIdx.x * 8 + wid, b = blockIdx.y;
    size_t rb = ((size_t)b * Ndim + n) * Pdim;
    const float4* row = (const float4*)(g_ZT + rb);
    float m = -3.4e38f;
#pragma unroll
    for (int i = 0; i < 16; i++) {
        float4 v = row[lane + 32 * i];
        m = fmaxf(m, fmaxf(fmaxf(v.x, v.y), fmaxf(v.z, v.w)));
    }
#pragma unroll
    for (int o = 16; o > 0; o >>= 1) m = fmaxf(m, __shfl_xor_sync(0xFFFFFFFFu, m, o));

    float s = 0.f;
    uint32_t cnt = 0;
    uint2* lst = g_list + rb;
#pragma unroll 2
    for (int i = 0; i < 16; i++) {
        int i4 = lane + 32 * i;
        float4 v = row[i4];
        float w4[4];
        w4[0] = __expf(v.x - m); w4[1] = __expf(v.y - m);
        w4[2] = __expf(v.z - m); w4[3] = __expf(v.w - m);
        s += (w4[0] + w4[1]) + (w4[2] + w4[3]);
#pragma unroll
        for (int j = 0; j < 4; j++) {
            bool keep = (w4[j] > THR);
            unsigned msk = __ballot_sync(0xFFFFFFFFu, keep);
            if (keep) {
                int off = __popc(msk & ((1u << lane) - 1u));
                lst[cnt + off] = make_uint2((unsigned)(i4 * 4 + j),
                                            __float_as_uint(w4[j]));
            }
            cnt += (uint32_t)__popc(msk);
        }
    }
#pragma unroll
    for (int o = 16; o > 0; o >>= 1) s += __shfl_xor_sync(0xFFFFFFFFu, s, o);
    if (lane == 0) {
        g_inv[(size_t)b * Ndim + n] = 1.0f / s;
        g_cnt[(size_t)b * Ndim + n] = (int)cnt;
    }
}

// ---------------------------------------------------------------------------
// K3 sparse: warp-per-(b,n). out[b][n][d] = inv * sum_j w_j * protoC[p_j][d] + 0.5
// proto rows are 2KB fp16 (g_p = 4MB, L2-resident). Iterations are independent
// except for the fp32 accumulators, so unroll-4 batches 4 entries' loads.
// ---------------------------------------------------------------------------
__global__ __launch_bounds__(256) void k3_sparse(float* __restrict__ out) {
    int wid = threadIdx.x >> 5, lane = threadIdx.x & 31;
    int n = blockIdx.x * 8 + wid, b = blockIdx.y;
    size_t rn = (size_t)b * Ndim + n;
    const uint2* __restrict__ lst = g_list + rn * Pdim;
    const int L = g_cnt[rn];
    const float inv = g_inv[rn];

    float acc[32];
#pragma unroll
    for (int k = 0; k < 32; k++) acc[k] = 0.f;

#pragma unroll 4
    for (int j = 0; j < L; j++) {
        uint2 e = lst[j];                       // broadcast load
        float w = __uint_as_float(e.y);
        const uint4* __restrict__ prow = (const uint4*)(g_p + (size_t)e.x * Ddim);
        uint4 pk[4];
#pragma unroll
        for (int q = 0; q < 4; q++) pk[q] = prow[lane + 32 * q];   // batched loads
#pragma unroll
        for (int q = 0; q < 4; q++) {
            const __half2* h = (const __half2*)&pk[q];
#pragma unroll
            for (int t = 0; t < 4; t++) {
                float2 f = __half22float2(h[t]);
                acc[q * 8 + t * 2 + 0] = fmaf(w, f.x, acc[q * 8 + t * 2 + 0]);
                acc[q * 8 + t * 2 + 1] = fmaf(w, f.y, acc[q * 8 + t * 2 + 1]);
            }
        }
    }

    float* orow = out + rn * Ddim;
#pragma unroll
    for (int q = 0; q < 4; q++) {
        int d0 = (lane + 32 * q) * 8;
        float4 o0, o1;
        o0.x = acc[q * 8 + 0] * inv + 0.5f; o0.y = acc[q * 8 + 1] * inv + 0.5f;
        o0.z = acc[q * 8 + 2] * inv + 0.5f; o0.w = acc[q * 8 + 3] * inv + 0.5f;
        o1.x = acc[q * 8 + 4] * inv + 0.5f; o1.y = acc[q * 8 + 5] * inv + 0.5f;
        o1.z = acc[q * 8 + 6] * inv + 0.5f; o1.w = acc[q * 8 + 7] * inv + 0.5f;
        *(float4*)(orow + d0) = o0;
        *(float4*)(orow + d0 + 4) = o1;
    }
}

// ---------------------------------------------------------------------------
extern "C" void kernel_launch(void* const* d_in, const int* in_sizes, int n_in,
                              void* d_out, int out_size)
{
    (void)in_sizes; (void)n_in; (void)out_size;
    const float* x     = (const float*)d_in[0];  // [B, N, D]
    const float* u     = (const float*)d_in[1];  // [B, P, N]
    const float* proto = (const float*)d_in[2];  // [P, D]
    float* out = (float*)d_out;                  // [B, N, D]

    cudaFuncSetAttribute(k1_logits, cudaFuncAttributeMaxDynamicSharedMemorySize, DYN_SMEM);

    quant_x<<<(Bdim * Ndim) / 8, 256>>>(x);
    quant_p<<<(Pdim * Ddim) / 256, 256>>>(proto);

    dim3 g1(Ndim / 128, Pdim / 128, Bdim);
    k1_logits<<<g1, 256, DYN_SMEM>>>(u);

    dim3 g2(Ndim / 8, Bdim);
    k2_softmax<<<g2, 256>>>();

    dim3 g3(Ndim / 8, Bdim);
    k3_sparse<<<g3, 256>>>(out);
}

// round 12
// speedup vs baseline: 1.8757x; 1.0970x over previous
#include <cuda_runtime.h>
#include <cuda_fp16.h>
#include <cstdint>

#define Bdim 16
#define Ndim 2048
#define Ddim 1024
#define Pdim 2048

// ---------------- device scratch (static; allocation-free rule) ----------------
__device__ __align__(256) __half g_x[(size_t)Bdim * Ndim * Ddim];    // x fp16 [b][n][d]
__device__ __align__(256) __half g_p[(size_t)Pdim * Ddim];           // (proto-0.5) [p][d]
__device__ __align__(256) float  g_ZT[(size_t)Bdim * Ndim * Pdim];   // Z^T [b][n][p]
__device__ __align__(256) uint2  g_list[(size_t)Bdim * Ndim * Pdim]; // (p, w) survivors
__device__ __align__(256) int    g_cnt[(size_t)Bdim * Ndim];         // survivors per (b,n)
__device__ __align__(256) float  g_rs[(size_t)Bdim * Ndim];          // 0.5 * row-sum of x
__device__ __align__(256) float  g_inv[(size_t)Bdim * Ndim];         // 1/sum_exp (full)
__device__ __align__(256) unsigned g_maxi[(size_t)Bdim * Ndim];      // ordered-uint max(z)

// ---------------- baseline-PTX helpers (sm_80-class only) ----------------------
__device__ __forceinline__ uint32_t smem_u32_of(const void* p) {
    uint32_t a;
    asm("{ .reg .u64 t; cvta.to.shared.u64 t, %1; cvt.u32.u64 %0, t; }" : "=r"(a) : "l"(p));
    return a;
}
__device__ __forceinline__ void cpasync16(uint32_t s, const void* g) {
    asm volatile("cp.async.cg.shared.global [%0], [%1], 16;" :: "r"(s), "l"(g));
}
#define CP_COMMIT() asm volatile("cp.async.commit_group;")
#define CP_WAIT(n)  asm volatile("cp.async.wait_group %0;" :: "n"(n))

__device__ __forceinline__ void ldsm4(uint32_t* r, uint32_t addr) {
    asm volatile("ldmatrix.sync.aligned.m8n8.x4.shared.b16 {%0,%1,%2,%3}, [%4];"
                 : "=r"(r[0]), "=r"(r[1]), "=r"(r[2]), "=r"(r[3]) : "r"(addr));
}
__device__ __forceinline__ void mma16816(float* c, const uint32_t* a, const uint32_t* b) {
    asm volatile("mma.sync.aligned.m16n8k16.row.col.f32.f16.f16.f32 "
                 "{%0,%1,%2,%3}, {%4,%5,%6,%7}, {%8,%9}, {%0,%1,%2,%3};"
                 : "+f"(c[0]), "+f"(c[1]), "+f"(c[2]), "+f"(c[3])
                 : "r"(a[0]), "r"(a[1]), "r"(a[2]), "r"(a[3]), "r"(b[0]), "r"(b[1]));
}

// ordered-uint encoding of fp32: monotone bijection, exact max via atomicMax
__device__ __forceinline__ unsigned enc_f(float f) {
    unsigned u = __float_as_uint(f);
    return (u & 0x80000000u) ? ~u : (u | 0x80000000u);
}
__device__ __forceinline__ float dec_f(unsigned k) {
    return __uint_as_float((k & 0x80000000u) ? (k & 0x7FFFFFFFu) : ~k);
}

// ---------------- tiling constants (R7 proven config) ----------------
static constexpr int KT = 64;                 // fp16 k per stage (128 data bytes/row)
static constexpr int ROWB = 144;              // padded smem row bytes (128 + 16)
static constexpr int TILE_B = 128 * ROWB;     // 18432 per operand tile
static constexpr int STAGE_B = 2 * TILE_B;    // A, B = 36864
static constexpr int NSTG = 3;                // circular pipeline depth
static constexpr int DYN_SMEM = NSTG * STAGE_B;   // 110592

static constexpr float THR = 1e-3f;           // survivor threshold on exp(z - max)

// load one stage (2 tiles x 128 rows x 128B), 8 cp.async per thread (256 thr)
__device__ __forceinline__ void load_stage(
    const __half* gA, const __half* gB,
    size_t Ks, int k0, uint32_t sbase, int tid)
{
    const __half* G[2] = {gA, gB};
#pragma unroll
    for (int j = 0; j < 8; j++) {
        const int idx = tid + j * 256;        // 0..2047
        const int tile = idx >> 10;
        const int c = idx & 1023;
        const int row = c >> 3, q = c & 7;
        cpasync16(sbase + tile * TILE_B + row * ROWB + q * 16,
                  G[tile] + (size_t)row * Ks + k0 + q * 8);
    }
}

// compute one k64 stage: 4 k16-steps x (4 m-frags x 4 n-frags)
__device__ __forceinline__ void compute_stage(
    uint32_t sbase, int wm, int wn, uint32_t aoff, uint32_t boff,
    float acc[4][4][4])
{
    const uint32_t sA = sbase;
    const uint32_t sB = sbase + TILE_B;
#pragma unroll
    for (int ks = 0; ks < 4; ks++) {
        const uint32_t kb = ks * 32;
        uint32_t bf[8];
#pragma unroll
        for (int f = 0; f < 2; f++) {
            uint32_t off = (wn * 32 + f * 16) * ROWB + kb + boff;
            ldsm4(bf + f * 4, sB + off);
        }
#pragma unroll
        for (int mf = 0; mf < 4; mf++) {
            uint32_t off = (wm * 64 + mf * 16) * ROWB + kb + aoff;
            uint32_t af[4];
            ldsm4(af, sA + off);
#pragma unroll
            for (int nf = 0; nf < 4; nf++)
                mma16816(acc[mf][nf], af, bf + nf * 2);
        }
    }
}

// 3-stage circular pipeline, one __syncthreads per stage
__device__ __forceinline__ void gemm_mainloop(
    const __half* gA, const __half* gB,
    size_t Ks, int T, uint32_t smem_b, int tid, float acc[4][4][4])
{
    const int lane = tid & 31, wid = tid >> 5;
    const int wm = wid & 1, wn = wid >> 1;
    const uint32_t aoff = (uint32_t)((lane & 15) * ROWB + ((lane & 16) ? 16 : 0));
    const uint32_t boff = (uint32_t)(((lane & 7) + ((lane & 16) ? 8 : 0)) * ROWB
                                     + ((lane & 8) ? 16 : 0));
#pragma unroll
    for (int mf = 0; mf < 4; mf++)
#pragma unroll
        for (int nf = 0; nf < 4; nf++)
#pragma unroll
            for (int e = 0; e < 4; e++) acc[mf][nf][e] = 0.f;

    load_stage(gA, gB, Ks, 0, smem_b, tid);
    CP_COMMIT();
    load_stage(gA, gB, Ks, KT, smem_b + STAGE_B, tid);
    CP_COMMIT();

    int s_cur = 0, s_nxt = 2;
    for (int t = 0; t < T; t++) {
        if (t == T - 1) { CP_WAIT(0); } else { CP_WAIT(1); }
        __syncthreads();
        if (t + 2 < T) {
            load_stage(gA, gB, Ks, (t + 2) * KT, smem_b + s_nxt * STAGE_B, tid);
            CP_COMMIT();
        }
        compute_stage(smem_b + s_cur * STAGE_B, wm, wn, aoff, boff, acc);
        s_cur = (s_cur == 2) ? 0 : s_cur + 1;
        s_nxt = (s_nxt == 2) ? 0 : s_nxt + 1;
    }
}

// ---------------------------------------------------------------------------
// init_max: reset per-(b,n) running max to encode(-FLT_MAX) = 0x00800000
// ---------------------------------------------------------------------------
__global__ __launch_bounds__(256) void init_max() {
    g_maxi[blockIdx.x * 256 + threadIdx.x] = 0x00800000u;
}

// ---------------------------------------------------------------------------
// quant_x: x -> fp16, plus 0.5*row-sum (exact fp32) for the centering correction
// ---------------------------------------------------------------------------
__global__ __launch_bounds__(256) void quant_x(const float* __restrict__ x) {
    const int w = blockIdx.x * 8 + (threadIdx.x >> 5);
    const int lane = threadIdx.x & 31;
    const float4* row = (const float4*)(x + (size_t)w * Ddim);
    float s = 0.f;
#pragma unroll
    for (int i = 0; i < 8; i++) {
        float4 v = row[lane + 32 * i];
        s += (v.x + v.y) + (v.z + v.w);
        __half2 h01 = __floats2half2_rn(v.x, v.y);
        __half2 h23 = __floats2half2_rn(v.z, v.w);
        __half2* o = (__half2*)(g_x + (size_t)w * Ddim + (lane + 32 * i) * 4);
        o[0] = h01; o[1] = h23;
    }
#pragma unroll
    for (int o = 16; o > 0; o >>= 1) s += __shfl_xor_sync(0xFFFFFFFFu, s, o);
    if (lane == 0) g_rs[w] = 0.5f * s;
}
// quant_p: (proto - 0.5) -> fp16 row-major (k1 B-operand and sparse k3 rows)
__global__ __launch_bounds__(256) void quant_p(const float* __restrict__ proto) {
    int idx = blockIdx.x * 256 + threadIdx.x;
    g_p[idx] = __float2half_rn(proto[idx] - 0.5f);
}

// ---------------------------------------------------------------------------
// K1: Z^T[b][n][p] = x.(proto-0.5)^T + 0.5*rowsum(x) + gumbel, plus per-(b,n)
// running max via ordered-uint atomicMax (quad-reduced first).
// ---------------------------------------------------------------------------
__global__ __launch_bounds__(256, 2) void k1_logits(const float* __restrict__ u) {
    extern __shared__ char smem[];
    const uint32_t smem_b = smem_u32_of(smem);
    const int tid = threadIdx.x, lane = tid & 31, wid = tid >> 5;
    const int wm = wid & 1, wn = wid >> 1;
    const int bn = blockIdx.x, bp = blockIdx.y, b = blockIdx.z;

    float acc[4][4][4];
    gemm_mainloop(g_x + ((size_t)b * Ndim + bn * 128) * Ddim,
                  g_p + (size_t)(bp * 128) * Ddim,
                  (size_t)Ddim, Ddim / KT, smem_b, tid, acc);

    __syncthreads();
    float* u_s = (float*)smem;
    const float* ug = u + ((size_t)b * Pdim + (size_t)bp * 128) * Ndim + bn * 128;
#pragma unroll
    for (int j = 0; j < 16; j++) {
        int idx = tid + j * 256;
        int row = idx >> 5, c4 = idx & 31;
        float4 v = *(const float4*)(ug + (size_t)row * Ndim + c4 * 4);
        *(float4*)(u_s + row * 132 + c4 * 4) = v;
    }
    __syncthreads();

    const int gID = lane >> 2, tg = lane & 3;
#pragma unroll
    for (int mf = 0; mf < 4; mf++) {
#pragma unroll
        for (int r2 = 0; r2 < 2; r2++) {
            const int nl = wm * 64 + mf * 16 + gID + r2 * 8;
            const size_t rn = (size_t)b * Ndim + bn * 128 + nl;
            const float rsv = g_rs[rn];
            const size_t rowbase = rn * Pdim + bp * 128;
            float zmax = -3.4e38f;
#pragma unroll
            for (int nf = 0; nf < 4; nf++) {
                const int pl = wn * 32 + nf * 8 + tg * 2;
                float u0 = u_s[pl * 132 + nl];
                float u1 = u_s[(pl + 1) * 132 + nl];
                float2 z;
                z.x = acc[mf][nf][r2 * 2 + 0] + rsv - __logf(-__logf(u0));
                z.y = acc[mf][nf][r2 * 2 + 1] + rsv - __logf(-__logf(u1));
                *(float2*)&g_ZT[rowbase + pl] = z;
                zmax = fmaxf(zmax, fmaxf(z.x, z.y));
            }
            // reduce over the quad (tg = lane&3): lanes in a quad share nl
            zmax = fmaxf(zmax, __shfl_xor_sync(0xFFFFFFFFu, zmax, 1));
            zmax = fmaxf(zmax, __shfl_xor_sync(0xFFFFFFFFu, zmax, 2));
            if (tg == 0) atomicMax(&g_maxi[rn], enc_f(zmax));
        }
    }
}

// ---------------------------------------------------------------------------
// K2: single-pass softmax using precomputed max; deterministic ballot
// compaction of survivors (w > THR); 1/sum over the FULL sum.
// ---------------------------------------------------------------------------
__global__ __launch_bounds__(256) void k2_softmax() {
    int wid = threadIdx.x >> 5, lane = threadIdx.x & 31;
    int n = blockIdx.x * 8 + wid, b = blockIdx.y;
    size_t rn = (size_t)b * Ndim + n;
    size_t rb = rn * Pdim;
    const float4* row = (const float4*)(g_ZT + rb);
    const float m = dec_f(g_maxi[rn]);   // exact max (ordered-uint bijection)

    float s = 0.f;
    uint32_t cnt = 0;
    uint2* lst = g_list + rb;
#pragma unroll 2
    for (int i = 0; i < 16; i++) {
        int i4 = lane + 32 * i;
        float4 v = row[i4];
        float w4[4];
        w4[0] = __expf(v.x - m); w4[1] = __expf(v.y - m);
        w4[2] = __expf(v.z - m); w4[3] = __expf(v.w - m);
        s += (w4[0] + w4[1]) + (w4[2] + w4[3]);
#pragma unroll
        for (int j = 0; j < 4; j++) {
            bool keep = (w4[j] > THR);
            unsigned msk = __ballot_sync(0xFFFFFFFFu, keep);
            if (keep) {
                int off = __popc(msk & ((1u << lane) - 1u));
                lst[cnt + off] = make_uint2((unsigned)(i4 * 4 + j),
                                            __float_as_uint(w4[j]));
            }
            cnt += (uint32_t)__popc(msk);
        }
    }
#pragma unroll
    for (int o = 16; o > 0; o >>= 1) s += __shfl_xor_sync(0xFFFFFFFFu, s, o);
    if (lane == 0) {
        g_inv[rn] = 1.0f / s;
        g_cnt[rn] = (int)cnt;
    }
}

// ---------------------------------------------------------------------------
// K3 sparse: warp-per-(b,n). out[b][n][d] = inv * sum_j w_j * protoC[p_j][d] + 0.5
// ---------------------------------------------------------------------------
__global__ __launch_bounds__(256) void k3_sparse(float* __restrict__ out) {
    int wid = threadIdx.x >> 5, lane = threadIdx.x & 31;
    int n = blockIdx.x * 8 + wid, b = blockIdx.y;
    size_t rn = (size_t)b * Ndim + n;
    const uint2* __restrict__ lst = g_list + rn * Pdim;
    const int L = g_cnt[rn];
    const float inv = g_inv[rn];

    float acc[32];
#pragma unroll
    for (int k = 0; k < 32; k++) acc[k] = 0.f;

#pragma unroll 4
    for (int j = 0; j < L; j++) {
        uint2 e = lst[j];                       // broadcast load
        float w = __uint_as_float(e.y);
        const uint4* __restrict__ prow = (const uint4*)(g_p + (size_t)e.x * Ddim);
        uint4 pk[4];
#pragma unroll
        for (int q = 0; q < 4; q++) pk[q] = prow[lane + 32 * q];   // batched loads
#pragma unroll
        for (int q = 0; q < 4; q++) {
            const __half2* h = (const __half2*)&pk[q];
#pragma unroll
            for (int t = 0; t < 4; t++) {
                float2 f = __half22float2(h[t]);
                acc[q * 8 + t * 2 + 0] = fmaf(w, f.x, acc[q * 8 + t * 2 + 0]);
                acc[q * 8 + t * 2 + 1] = fmaf(w, f.y, acc[q * 8 + t * 2 + 1]);
            }
        }
    }

    float* orow = out + rn * Ddim;
#pragma unroll
    for (int q = 0; q < 4; q++) {
        int d0 = (lane + 32 * q) * 8;
        float4 o0, o1;
        o0.x = acc[q * 8 + 0] * inv + 0.5f; o0.y = acc[q * 8 + 1] * inv + 0.5f;
        o0.z = acc[q * 8 + 2] * inv + 0.5f; o0.w = acc[q * 8 + 3] * inv + 0.5f;
        o1.x = acc[q * 8 + 4] * inv + 0.5f; o1.y = acc[q * 8 + 5] * inv + 0.5f;
        o1.z = acc[q * 8 + 6] * inv + 0.5f; o1.w = acc[q * 8 + 7] * inv + 0.5f;
        *(float4*)(orow + d0) = o0;
        *(float4*)(orow + d0 + 4) = o1;
    }
}

// ---------------------------------------------------------------------------
extern "C" void kernel_launch(void* const* d_in, const int* in_sizes, int n_in,
                              void* d_out, int out_size)
{
    (void)in_sizes; (void)n_in; (void)out_size;
    const float* x     = (const float*)d_in[0];  // [B, N, D]
    const float* u     = (const float*)d_in[1];  // [B, P, N]
    const float* proto = (const float*)d_in[2];  // [P, D]
    float* out = (float*)d_out;                  // [B, N, D]

    cudaFuncSetAttribute(k1_logits, cudaFuncAttributeMaxDynamicSharedMemorySize, DYN_SMEM);

    init_max<<<(Bdim * Ndim) / 256, 256>>>();
    quant_x<<<(Bdim * Ndim) / 8, 256>>>(x);
    quant_p<<<(Pdim * Ddim) / 256, 256>>>(proto);

    dim3 g1(Ndim / 128, Pdim / 128, Bdim);
    k1_logits<<<g1, 256, DYN_SMEM>>>(u);

    dim3 g2(Ndim / 8, Bdim);
    k2_softmax<<<g2, 256>>>();

    dim3 g3(Ndim / 8, Bdim);
    k3_sparse<<<g3, 256>>>(out);
}